// round 2
// baseline (speedup 1.0000x reference)
#include <cuda_runtime.h>

// out[b,f] = x[b,f] * (log_sigma[f] < 1.0f ? e : 1.0f)
// BATCH=65536, N_FEATURES=4096 -> 2^26 float4 elements. Pure HBM stream.
//
// Grid-stride persistent layout: total threads = 2^19, a multiple of
// VEC4_PER_ROW (1024), so each thread's column index is loop-invariant.
// The scale float4 is computed ONCE per thread; the loop body is pure
// LDG.128 -> 4x FMUL -> STG.128, unrolled x4 for MLP.

#define N_FEATURES   4096
#define VEC4_PER_ROW (N_FEATURES / 4)            // 1024, power of two
#define TOTAL_VEC4   (65536LL * VEC4_PER_ROW)    // 2^26

#define THREADS 256
#define BLOCKS  2048                              // 2^19 threads total
#define NTHREADS ((long long)THREADS * BLOCKS)    // 2^19, multiple of 1024
#define ITERS   (TOTAL_VEC4 / NTHREADS)           // 128, exact

__global__ void __launch_bounds__(THREADS)
svdropout2d_kernel(const float4* __restrict__ x,
                   const float4* __restrict__ log_sigma,
                   float4* __restrict__ out)
{
    const float E = 2.71828182845904523536f;

    const long long i0 = (long long)blockIdx.x * THREADS + threadIdx.x;

    // Column (float4 units) is invariant across the grid-stride loop
    // because NTHREADS is a multiple of VEC4_PER_ROW.
    const int c = (int)(i0 & (VEC4_PER_ROW - 1));
    const float4 ls = __ldg(&log_sigma[c]);

    float4 s;
    s.x = (ls.x < 1.0f) ? E : 1.0f;
    s.y = (ls.y < 1.0f) ? E : 1.0f;
    s.z = (ls.z < 1.0f) ? E : 1.0f;
    s.w = (ls.w < 1.0f) ? E : 1.0f;

    // 128 iterations, unrolled x4 -> 32 groups of 4 independent loads (MLP=4)
    #pragma unroll 1
    for (int g = 0; g < (int)(ITERS / 4); ++g) {
        long long base = i0 + (long long)g * (4 * NTHREADS);

        float4 v0 = __ldcs(&x[base + 0 * NTHREADS]);
        float4 v1 = __ldcs(&x[base + 1 * NTHREADS]);
        float4 v2 = __ldcs(&x[base + 2 * NTHREADS]);
        float4 v3 = __ldcs(&x[base + 3 * NTHREADS]);

        v0.x *= s.x; v0.y *= s.y; v0.z *= s.z; v0.w *= s.w;
        v1.x *= s.x; v1.y *= s.y; v1.z *= s.z; v1.w *= s.w;
        v2.x *= s.x; v2.y *= s.y; v2.z *= s.z; v2.w *= s.w;
        v3.x *= s.x; v3.y *= s.y; v3.z *= s.z; v3.w *= s.w;

        __stcs(&out[base + 0 * NTHREADS], v0);
        __stcs(&out[base + 1 * NTHREADS], v1);
        __stcs(&out[base + 2 * NTHREADS], v2);
        __stcs(&out[base + 3 * NTHREADS], v3);
    }
}

extern "C" void kernel_launch(void* const* d_in, const int* in_sizes, int n_in,
                              void* d_out, int out_size)
{
    const float4* x  = (const float4*)d_in[0];
    const float4* ls = (const float4*)d_in[1];
    float4* out      = (float4*)d_out;

    svdropout2d_kernel<<<BLOCKS, THREADS>>>(x, ls, out);
}

// round 3
// speedup vs baseline: 1.0289x; 1.0289x over previous
#include <cuda_runtime.h>

// out[b,f] = x[b,f] * (log_sigma[f] < 1.0f ? e : 1.0f)
// BATCH=65536, N_FEATURES=4096 -> 2^26 float4. Pure HBM stream (2.15 GB).
//
// R3: grid-stride with FINE granularity (8192 blocks ≈ 55/SM) to fix the
// tail imbalance of R2's 2048 long-running blocks, while keeping the
// loop-invariant column/scale (total threads 2^21 is a multiple of 1024).

#define N_FEATURES   4096
#define VEC4_PER_ROW (N_FEATURES / 4)            // 1024, power of two
#define TOTAL_VEC4   (65536LL * VEC4_PER_ROW)    // 2^26

#define THREADS  256
#define BLOCKS   8192                             // 2^21 threads total
#define NTHREADS ((long long)THREADS * BLOCKS)    // 2^21, multiple of 1024
#define ITERS    (TOTAL_VEC4 / NTHREADS)          // 32, exact

__global__ void __launch_bounds__(THREADS)
svdropout2d_kernel(const float4* __restrict__ x,
                   const float4* __restrict__ log_sigma,
                   float4* __restrict__ out)
{
    const float E = 2.71828182845904523536f;

    const long long i0 = (long long)blockIdx.x * THREADS + threadIdx.x;

    // Column (float4 units) invariant across the loop (stride % 1024 == 0)
    const int c = (int)(i0 & (VEC4_PER_ROW - 1));
    const float4 ls = __ldg(&log_sigma[c]);

    float4 s;
    s.x = (ls.x < 1.0f) ? E : 1.0f;
    s.y = (ls.y < 1.0f) ? E : 1.0f;
    s.z = (ls.z < 1.0f) ? E : 1.0f;
    s.w = (ls.w < 1.0f) ? E : 1.0f;

    // 32 iterations, grouped x4 for MLP=4 independent in-flight loads
    #pragma unroll 1
    for (int g = 0; g < (int)(ITERS / 4); ++g) {
        long long base = i0 + (long long)g * (4 * NTHREADS);

        float4 v0 = __ldcs(&x[base + 0 * NTHREADS]);
        float4 v1 = __ldcs(&x[base + 1 * NTHREADS]);
        float4 v2 = __ldcs(&x[base + 2 * NTHREADS]);
        float4 v3 = __ldcs(&x[base + 3 * NTHREADS]);

        v0.x *= s.x; v0.y *= s.y; v0.z *= s.z; v0.w *= s.w;
        v1.x *= s.x; v1.y *= s.y; v1.z *= s.z; v1.w *= s.w;
        v2.x *= s.x; v2.y *= s.y; v2.z *= s.z; v2.w *= s.w;
        v3.x *= s.x; v3.y *= s.y; v3.z *= s.z; v3.w *= s.w;

        __stcs(&out[base + 0 * NTHREADS], v0);
        __stcs(&out[base + 1 * NTHREADS], v1);
        __stcs(&out[base + 2 * NTHREADS], v2);
        __stcs(&out[base + 3 * NTHREADS], v3);
    }
}

extern "C" void kernel_launch(void* const* d_in, const int* in_sizes, int n_in,
                              void* d_out, int out_size)
{
    const float4* x  = (const float4*)d_in[0];
    const float4* ls = (const float4*)d_in[1];
    float4* out      = (float4*)d_out;

    svdropout2d_kernel<<<BLOCKS, THREADS>>>(x, ls, out);
}